// round 6
// baseline (speedup 1.0000x reference)
#include <cuda_runtime.h>
#include <math.h>

#define Bb 4
#define Ss 2048
#define Dd 1024
#define Hh 16
#define KD 64
#define Pp 1024

// Scratch (static __device__ per allocation rules)
__device__ float g_q[Bb*Hh*Ss*KD];     // [B,H,S,Kd]
__device__ float g_k[Bb*Hh*Ss*KD];
__device__ float g_v[Bb*Hh*Ss*KD];
__device__ float g_att[Bb*Ss*Pp];      // [B,S,P] concat

// ---------------------------------------------------------------------------
// GEMM: C = A[M,K] @ W[K,N] + bias.  M=8192, K=1024, N=1024.
// scatter=1: write to [B,H,S,Kd] layout; scatter=0: plain row-major.
// ---------------------------------------------------------------------------
#define BM 128
#define BN 64
#define BKK 16

__global__ __launch_bounds__(256) void gemm_kernel(
    const float* __restrict__ A, const float* __restrict__ W,
    const float* __restrict__ bias, float* __restrict__ C, int scatter)
{
    __shared__ float As[BKK][BM];
    __shared__ float Wsm[BKK][BN];
    const int tid = threadIdx.x;
    const int tn = tid & 15;     // 0..15 (N dim)
    const int tm = tid >> 4;     // 0..15 (M dim)
    const int blockN = blockIdx.x * BN;
    const int blockM = blockIdx.y * BM;
    const int K = Dd, N = Pp;

    float acc[8][4];
    #pragma unroll
    for (int i = 0; i < 8; i++)
        #pragma unroll
        for (int j = 0; j < 4; j++) acc[i][j] = 0.f;

    for (int k0 = 0; k0 < K; k0 += BKK) {
        // A tile: 128 rows x 16 cols = 512 float4, 2 per thread
        #pragma unroll
        for (int r = 0; r < 2; r++) {
            int idx = tid + r * 256;     // 0..511
            int m   = idx >> 2;          // 0..127
            int k4  = idx & 3;           // 0..3
            float4 v = *(const float4*)&A[(size_t)(blockM + m) * K + k0 + k4 * 4];
            As[k4*4+0][m] = v.x;
            As[k4*4+1][m] = v.y;
            As[k4*4+2][m] = v.z;
            As[k4*4+3][m] = v.w;
        }
        // W tile: 16 rows x 64 cols = 256 float4, 1 per thread
        {
            int kk = tid >> 4;           // 0..15
            int n4 = tid & 15;           // 0..15
            float4 v = *(const float4*)&W[(size_t)(k0 + kk) * N + blockN + n4 * 4];
            *(float4*)&Wsm[kk][n4*4] = v;
        }
        __syncthreads();
        #pragma unroll
        for (int kk = 0; kk < BKK; kk++) {
            float ra[8], rw[4];
            #pragma unroll
            for (int i = 0; i < 8; i++) ra[i] = As[kk][tm*8 + i];
            #pragma unroll
            for (int j = 0; j < 4; j++) rw[j] = Wsm[kk][tn*4 + j];
            #pragma unroll
            for (int i = 0; i < 8; i++)
                #pragma unroll
                for (int j = 0; j < 4; j++)
                    acc[i][j] += ra[i] * rw[j];
        }
        __syncthreads();
    }

    #pragma unroll
    for (int i = 0; i < 8; i++) {
        int m = blockM + tm*8 + i;
        #pragma unroll
        for (int j = 0; j < 4; j++) {
            int n = blockN + tn*4 + j;
            float val = acc[i][j] + bias[n];
            if (!scatter) {
                C[(size_t)m * N + n] = val;
            } else {
                int b = m >> 11;       // /2048
                int s = m & 2047;
                int h = n >> 6;        // /64
                int d = n & 63;
                C[(((size_t)(b*Hh + h)) * Ss + s) * KD + d] = val;
            }
        }
    }
}

// ---------------------------------------------------------------------------
// Fused causal+ALiBi flash attention, fp32.
// Grid: (S/128, B*H), block 128 threads. One query row per thread.
// Dynamic smem: Ks[64*64] + Vs[64*64] + Sscr[64*128] = 64 KB
// ---------------------------------------------------------------------------
__global__ __launch_bounds__(128) void attn_kernel(
    const float* __restrict__ Qg, const float* __restrict__ Kg,
    const float* __restrict__ Vg, float* __restrict__ Out)
{
    extern __shared__ float smem[];
    float* Ks   = smem;                // 64*64
    float* Vs   = smem + 64*64;        // 64*64
    float* Sscr = smem + 2*64*64;      // 64*128

    const int tid = threadIdx.x;
    const int bh  = blockIdx.y;        // b*H + h
    const int h   = bh & (Hh - 1);
    const int b   = bh >> 4;
    const int qi  = blockIdx.x * 128 + tid;   // query row in sequence

    // load this thread's q row into registers
    float q[KD];
    {
        const float* qb = Qg + (((size_t)bh) * Ss + qi) * KD;
        #pragma unroll
        for (int d4 = 0; d4 < 16; d4++) {
            float4 v = *(const float4*)&qb[d4*4];
            q[d4*4+0] = v.x; q[d4*4+1] = v.y; q[d4*4+2] = v.z; q[d4*4+3] = v.w;
        }
    }
    float o[KD];
    #pragma unroll
    for (int d = 0; d < KD; d++) o[d] = 0.f;

    float mrun = -1e30f, lrun = 0.f;
    const float slope = exp2f(-0.5f * (float)(h + 1));

    const int ntiles = 2 * blockIdx.x + 2;   // causal: last key tile covers row qi
    for (int jt = 0; jt < ntiles; jt++) {
        const int jbase = jt * 64;
        const float* kb = Kg + (((size_t)bh) * Ss + jbase) * KD;
        const float* vb = Vg + (((size_t)bh) * Ss + jbase) * KD;
        __syncthreads();   // previous tile's PV reads done before overwrite
        #pragma unroll
        for (int r = 0; r < 8; r++) {
            int idx = tid + r * 128;         // float4 index 0..1023
            *(float4*)&Ks[idx*4] = *(const float4*)&kb[idx*4];
            *(float4*)&Vs[idx*4] = *(const float4*)&vb[idx*4];
        }
        __syncthreads();

        if (jbase > qi) continue;   // tile fully masked for this thread

        // ---- scores ----
        float smax = -1e30f;
        for (int j = 0; j < 64; j++) {
            const int jg = jbase + j;
            float s;
            if (jg > qi) {
                s = -1e30f;
            } else {
                float d0 = 0.f, d1 = 0.f, d2 = 0.f, d3 = 0.f;
                #pragma unroll
                for (int d4 = 0; d4 < 16; d4++) {
                    float4 kv = *(const float4*)&Ks[j*64 + d4*4];  // broadcast
                    d0 += q[d4*4+0] * kv.x;
                    d1 += q[d4*4+1] * kv.y;
                    d2 += q[d4*4+2] * kv.z;
                    d3 += q[d4*4+3] * kv.w;
                }
                s = (d0 + d1 + d2 + d3) * 0.125f + slope * (float)(qi - jg);
            }
            Sscr[j*128 + tid] = s;
            smax = fmaxf(smax, s);
        }

        const float m_new = fmaxf(mrun, smax);
        const float corr  = __expf(mrun - m_new);
        lrun *= corr;
        #pragma unroll
        for (int d = 0; d < KD; d++) o[d] *= corr;

        // ---- PV ----
        for (int j = 0; j < 64; j++) {
            float p = __expf(Sscr[j*128 + tid] - m_new);
            lrun += p;
            #pragma unroll
            for (int d4 = 0; d4 < 16; d4++) {
                float4 vv = *(const float4*)&Vs[j*64 + d4*4];      // broadcast
                o[d4*4+0] += p * vv.x;
                o[d4*4+1] += p * vv.y;
                o[d4*4+2] += p * vv.z;
                o[d4*4+3] += p * vv.w;
            }
        }
        mrun = m_new;
    }

    // write concat output: [B, S, H*Kd]
    const float inv = 1.f / lrun;
    float* ob = Out + ((size_t)(b * Ss + qi)) * Pp + h * KD;
    #pragma unroll
    for (int d4 = 0; d4 < 16; d4++) {
        float4 v;
        v.x = o[d4*4+0] * inv;
        v.y = o[d4*4+1] * inv;
        v.z = o[d4*4+2] * inv;
        v.w = o[d4*4+3] * inv;
        *(float4*)&ob[d4*4] = v;
    }
}

// ---------------------------------------------------------------------------
extern "C" void kernel_launch(void* const* d_in, const int* in_sizes, int n_in,
                              void* d_out, int out_size)
{
    const float* query = (const float*)d_in[0];
    const float* key   = (const float*)d_in[1];
    const float* value = (const float*)d_in[2];
    const float* Wq    = (const float*)d_in[3];
    const float* bq    = (const float*)d_in[4];
    const float* Wk    = (const float*)d_in[5];
    const float* bk    = (const float*)d_in[6];
    const float* Wv    = (const float*)d_in[7];
    const float* bv    = (const float*)d_in[8];
    const float* Wo    = (const float*)d_in[9];
    const float* bo    = (const float*)d_in[10];
    float* out = (float*)d_out;

    float *qs, *ks, *vs, *att;
    cudaGetSymbolAddress((void**)&qs,  g_q);
    cudaGetSymbolAddress((void**)&ks,  g_k);
    cudaGetSymbolAddress((void**)&vs,  g_v);
    cudaGetSymbolAddress((void**)&att, g_att);

    dim3 ggrid(Pp / BN, (Bb * Ss) / BM);   // (16, 64)
    gemm_kernel<<<ggrid, 256>>>(query, Wq, bq, qs, 1);
    gemm_kernel<<<ggrid, 256>>>(key,   Wk, bk, ks, 1);
    gemm_kernel<<<ggrid, 256>>>(value, Wv, bv, vs, 1);

    static int smem_set = 0;
    const int attn_smem = (64*64 + 64*64 + 64*128) * (int)sizeof(float);  // 64 KB
    if (!smem_set) {
        cudaFuncSetAttribute(attn_kernel,
                             cudaFuncAttributeMaxDynamicSharedMemorySize, attn_smem);
        smem_set = 1;
    }
    dim3 agrid(Ss / 128, Bb * Hh);         // (16, 64)
    attn_kernel<<<agrid, 128, attn_smem>>>(qs, ks, vs, att);

    gemm_kernel<<<ggrid, 256>>>(att, Wo, bo, out, 0);
}

// round 8
// speedup vs baseline: 1.4909x; 1.4909x over previous
#include <cuda_runtime.h>
#include <cuda_bf16.h>
#include <math.h>
#include <stdint.h>

#define Bb 4
#define Ss 2048
#define Dd 1024
#define Hh 16
#define KD 64
#define Pp 1024

// ---------------- scratch (static __device__ per allocation rules) ----------
__device__ float g_q[Bb*Hh*Ss*KD];     // [B,H,S,Kd]
__device__ float g_k[Bb*Hh*Ss*KD];
__device__ float g_v[Bb*Hh*Ss*KD];
__device__ float g_att[Bb*Ss*Pp];      // [B,S,P] concat

__device__ __nv_bfloat16 g_ahi[Bb*Ss*Dd];   // activation split (reused per GEMM)
__device__ __nv_bfloat16 g_alo[Bb*Ss*Dd];
__device__ __nv_bfloat16 g_whi[Dd*Pp];      // transposed weight split [N][K]
__device__ __nv_bfloat16 g_wlo[Dd*Pp];

// ---------------------------------------------------------------------------
// helpers (base-target instructions only: mma.sync / ldmatrix / cp.async)
// ---------------------------------------------------------------------------
__device__ __forceinline__ uint32_t smem_u32(const void* p){
    uint32_t a;
    asm("{ .reg .u64 t; cvta.to.shared.u64 t, %1; cvt.u32.u64 %0, t; }" : "=r"(a) : "l"(p));
    return a;
}
__device__ __forceinline__ void cp16(uint32_t s, const void* g){
    asm volatile("cp.async.cg.shared.global [%0], [%1], 16;"
                 :: "r"(s), "l"(__cvta_generic_to_global(g)) : "memory");
}
__device__ __forceinline__ void ldsm4(uint32_t* d, uint32_t addr){
    asm volatile("ldmatrix.sync.aligned.m8n8.x4.shared.b16 {%0,%1,%2,%3}, [%4];"
                 : "=r"(d[0]), "=r"(d[1]), "=r"(d[2]), "=r"(d[3]) : "r"(addr));
}
__device__ __forceinline__ void mma16816(float* c, const uint32_t* a, const uint32_t* b){
    asm volatile("mma.sync.aligned.m16n8k16.row.col.f32.bf16.bf16.f32 "
                 "{%0,%1,%2,%3}, {%4,%5,%6,%7}, {%8,%9}, {%0,%1,%2,%3};"
                 : "+f"(c[0]), "+f"(c[1]), "+f"(c[2]), "+f"(c[3])
                 : "r"(a[0]), "r"(a[1]), "r"(a[2]), "r"(a[3]), "r"(b[0]), "r"(b[1]));
}
// swizzled smem offset for tile row r (64B rows = 32 bf16), 16B chunk c (0..3)
__device__ __forceinline__ uint32_t swoff(int r, int c){
    return (uint32_t)(r * 64 + ((c ^ ((r >> 1) & 3)) << 4));
}

// ---------------------------------------------------------------------------
// split / transpose-split prep kernels
// ---------------------------------------------------------------------------
__global__ __launch_bounds__(256) void split_kernel(
    const float* __restrict__ X, __nv_bfloat162* __restrict__ hi,
    __nv_bfloat162* __restrict__ lo)
{
    int i = blockIdx.x * 256 + threadIdx.x;       // one float4 per thread
    float4 v = reinterpret_cast<const float4*>(X)[i];
    float f[4] = {v.x, v.y, v.z, v.w};
    __nv_bfloat16 h[4], l[4];
    #pragma unroll
    for (int j = 0; j < 4; j++){
        h[j] = __float2bfloat16(f[j]);
        l[j] = __float2bfloat16(f[j] - __bfloat162float(h[j]));
    }
    hi[i*2+0] = __nv_bfloat162(h[0], h[1]);
    hi[i*2+1] = __nv_bfloat162(h[2], h[3]);
    lo[i*2+0] = __nv_bfloat162(l[0], l[1]);
    lo[i*2+1] = __nv_bfloat162(l[2], l[3]);
}

// W [K=1024][N=1024] row-major -> Wt hi/lo [N][K]
__global__ __launch_bounds__(256) void tsplit_kernel(
    const float* __restrict__ W, __nv_bfloat16* __restrict__ th,
    __nv_bfloat16* __restrict__ tl)
{
    __shared__ float t[32][33];
    const int n0 = blockIdx.x * 32, k0 = blockIdx.y * 32;
    const int tx = threadIdx.x, ty = threadIdx.y;     // 32 x 8
    #pragma unroll
    for (int r = 0; r < 4; r++)
        t[ty + 8*r][tx] = W[(size_t)(k0 + ty + 8*r) * Pp + n0 + tx];
    __syncthreads();
    #pragma unroll
    for (int r = 0; r < 4; r++){
        float v = t[tx][ty + 8*r];                    // = W[k0+tx][n0+ty+8r]
        int n = n0 + ty + 8*r, k = k0 + tx;
        __nv_bfloat16 h = __float2bfloat16(v);
        th[(size_t)n * Dd + k] = h;
        tl[(size_t)n * Dd + k] = __float2bfloat16(v - __bfloat162float(h));
    }
}

// ---------------------------------------------------------------------------
// HMMA split-bf16 GEMM: C[M=8192,N=1024] = A @ W + bias
// A hi/lo bf16 [M][K]; W transposed hi/lo bf16 [N][K].
// Block 128x128, BK=32, 256 threads, 3-stage cp.async pipeline.
// ---------------------------------------------------------------------------
#define STB  32768              // stage bytes: 4 tiles x (128 x 32 bf16 = 8KB)
#define NSTG 3
#define NKI  (Dd / 32)          // 32 k-chunks

__device__ __forceinline__ void stage_load(
    uint32_t sb, const __nv_bfloat16* __restrict__ Ahi,
    const __nv_bfloat16* __restrict__ Alo,
    const __nv_bfloat16* __restrict__ Bhi,
    const __nv_bfloat16* __restrict__ Blo,
    int m0, int n0, int k0, int tid)
{
    #pragma unroll
    for (int half = 0; half < 2; half++){
        int idx = tid + half * 256;      // 0..511  (128 rows x 4 chunks)
        int r = idx >> 2, c = idx & 3;
        uint32_t so = swoff(r, c);
        size_t ga = (size_t)(m0 + r) * Dd + k0 + c * 8;
        size_t gb = (size_t)(n0 + r) * Dd + k0 + c * 8;
        cp16(sb +         so, Ahi + ga);
        cp16(sb +  8192 + so, Alo + ga);
        cp16(sb + 16384 + so, Bhi + gb);
        cp16(sb + 24576 + so, Blo + gb);
    }
}

__global__ __launch_bounds__(256) void gemm_mma_kernel(
    const __nv_bfloat16* __restrict__ Ahi, const __nv_bfloat16* __restrict__ Alo,
    const __nv_bfloat16* __restrict__ Bhi, const __nv_bfloat16* __restrict__ Blo,
    const float* __restrict__ bias, float* __restrict__ C, int scatter)
{
    extern __shared__ char dsm[];
    const uint32_t sbase = smem_u32(dsm);

    const int tid  = threadIdx.x;
    const int lane = tid & 31;
    const int wid  = tid >> 5;
    const int wm   = wid & 1;            // 0..1  (64 rows each)
    const int wn   = wid >> 1;           // 0..3  (32 cols each)
    const int n0 = blockIdx.x * 128;
    const int m0 = blockIdx.y * 128;

    float acc[4][4][4];
    #pragma unroll
    for (int i = 0; i < 4; i++)
        #pragma unroll
        for (int j = 0; j < 4; j++)
            #pragma unroll
            for (int k = 0; k < 4; k++) acc[i][j][k] = 0.f;

    stage_load(sbase,       Ahi, Alo, Bhi, Blo, m0, n0, 0,  tid);
    asm volatile("cp.async.commit_group;" ::: "memory");
    stage_load(sbase + STB, Ahi, Alo, Bhi, Blo, m0, n0, 32, tid);
    asm volatile("cp.async.commit_group;" ::: "memory");

    for (int kc = 0; kc < NKI; kc++){
        asm volatile("cp.async.wait_group 1;" ::: "memory");
        __syncthreads();

        if (kc + 2 < NKI)
            stage_load(sbase + (uint32_t)((kc + 2) % NSTG) * STB,
                       Ahi, Alo, Bhi, Blo, m0, n0, (kc + 2) * 32, tid);
        asm volatile("cp.async.commit_group;" ::: "memory");

        const uint32_t sb = sbase + (uint32_t)(kc % NSTG) * STB;
        #pragma unroll
        for (int ks = 0; ks < 2; ks++){
            uint32_t ah[4][4], al[4][4], bh[8], bl[8];
            #pragma unroll
            for (int mf = 0; mf < 4; mf++){
                int r = wm * 64 + mf * 16 + (lane & 15);
                int c = ks * 2 + (lane >> 4);
                uint32_t o = swoff(r, c);
                ldsm4(ah[mf], sb + o);
                ldsm4(al[mf], sb + 8192 + o);
            }
            #pragma unroll
            for (int p = 0; p < 2; p++){
                int r = wn * 32 + p * 16 + ((lane >> 4) << 3) + (lane & 7);
                int c = ks * 2 + ((lane >> 3) & 1);
                uint32_t o = swoff(r, c);
                ldsm4(&bh[p*4], sb + 16384 + o);
                ldsm4(&bl[p*4], sb + 24576 + o);
            }
            #pragma unroll
            for (int mf = 0; mf < 4; mf++)
                #pragma unroll
                for (int nf = 0; nf < 4; nf++){
                    mma16816(acc[mf][nf], ah[mf], &bh[nf*2]);
                    mma16816(acc[mf][nf], ah[mf], &bl[nf*2]);
                    mma16816(acc[mf][nf], al[mf], &bh[nf*2]);
                }
        }
    }

    // epilogue: c-frag rows = lane/4 (+8), cols = (lane%4)*2 (+1)
    #pragma unroll
    for (int mf = 0; mf < 4; mf++){
        #pragma unroll
        for (int nf = 0; nf < 4; nf++){
            const int col = n0 + wn * 32 + nf * 8 + (lane & 3) * 2;
            const float b0 = __ldg(&bias[col]), b1 = __ldg(&bias[col + 1]);
            #pragma unroll
            for (int half = 0; half < 2; half++){
                const int m = m0 + wm * 64 + mf * 16 + (lane >> 2) + half * 8;
                float v0 = acc[mf][nf][half*2 + 0] + b0;
                float v1 = acc[mf][nf][half*2 + 1] + b1;
                if (!scatter){
                    float2* dst = (float2*)&C[(size_t)m * Pp + col];
                    *dst = make_float2(v0, v1);
                } else {
                    const int b  = m >> 11;
                    const int sq = m & 2047;
                    const int h  = col >> 6;
                    const int d  = col & 63;
                    float2* dst = (float2*)&C[(((size_t)(b * Hh + h)) * Ss + sq) * KD + d];
                    *dst = make_float2(v0, v1);
                }
            }
        }
    }
}

// ---------------------------------------------------------------------------
// Fused causal+ALiBi flash attention, fp32 (unchanged — R5 best).
// ---------------------------------------------------------------------------
__global__ __launch_bounds__(128) void attn_kernel(
    const float* __restrict__ Qg, const float* __restrict__ Kg,
    const float* __restrict__ Vg, float* __restrict__ Out)
{
    extern __shared__ float smem[];
    float* Ks   = smem;                // 64*64
    float* Vs   = smem + 64*64;        // 64*64
    float* Sscr = smem + 2*64*64;      // 64*128

    const int tid = threadIdx.x;
    const int bh  = blockIdx.y;        // b*H + h
    const int h   = bh & (Hh - 1);
    const int b   = bh >> 4;
    const int qi  = blockIdx.x * 128 + tid;

    float q[KD];
    {
        const float* qb = Qg + (((size_t)bh) * Ss + qi) * KD;
        #pragma unroll
        for (int d4 = 0; d4 < 16; d4++) {
            float4 v = *(const float4*)&qb[d4*4];
            q[d4*4+0] = v.x; q[d4*4+1] = v.y; q[d4*4+2] = v.z; q[d4*4+3] = v.w;
        }
    }
    float o[KD];
    #pragma unroll
    for (int d = 0; d < KD; d++) o[d] = 0.f;

    float mrun = -1e30f, lrun = 0.f;
    const float slope = exp2f(-0.5f * (float)(h + 1));

    const int ntiles = 2 * blockIdx.x + 2;
    for (int jt = 0; jt < ntiles; jt++) {
        const int jbase = jt * 64;
        const float* kb = Kg + (((size_t)bh) * Ss + jbase) * KD;
        const float* vb = Vg + (((size_t)bh) * Ss + jbase) * KD;
        __syncthreads();
        #pragma unroll
        for (int r = 0; r < 8; r++) {
            int idx = tid + r * 128;
            *(float4*)&Ks[idx*4] = *(const float4*)&kb[idx*4];
            *(float4*)&Vs[idx*4] = *(const float4*)&vb[idx*4];
        }
        __syncthreads();

        if (jbase > qi) continue;

        float smax = -1e30f;
        for (int j = 0; j < 64; j++) {
            const int jg = jbase + j;
            float s;
            if (jg > qi) {
                s = -1e30f;
            } else {
                float d0 = 0.f, d1 = 0.f, d2 = 0.f, d3 = 0.f;
                #pragma unroll
                for (int d4 = 0; d4 < 16; d4++) {
                    float4 kv = *(const float4*)&Ks[j*64 + d4*4];
                    d0 += q[d4*4+0] * kv.x;
                    d1 += q[d4*4+1] * kv.y;
                    d2 += q[d4*4+2] * kv.z;
                    d3 += q[d4*4+3] * kv.w;
                }
                s = (d0 + d1 + d2 + d3) * 0.125f + slope * (float)(qi - jg);
            }
            Sscr[j*128 + tid] = s;
            smax = fmaxf(smax, s);
        }

        const float m_new = fmaxf(mrun, smax);
        const float corr  = __expf(mrun - m_new);
        lrun *= corr;
        #pragma unroll
        for (int d = 0; d < KD; d++) o[d] *= corr;

        for (int j = 0; j < 64; j++) {
            float p = __expf(Sscr[j*128 + tid] - m_new);
            lrun += p;
            #pragma unroll
            for (int d4 = 0; d4 < 16; d4++) {
                float4 vv = *(const float4*)&Vs[j*64 + d4*4];
                o[d4*4+0] += p * vv.x;
                o[d4*4+1] += p * vv.y;
                o[d4*4+2] += p * vv.z;
                o[d4*4+3] += p * vv.w;
            }
        }
        mrun = m_new;
    }

    const float inv = 1.f / lrun;
    float* ob = Out + ((size_t)(b * Ss + qi)) * Pp + h * KD;
    #pragma unroll
    for (int d4 = 0; d4 < 16; d4++) {
        float4 v;
        v.x = o[d4*4+0] * inv;
        v.y = o[d4*4+1] * inv;
        v.z = o[d4*4+2] * inv;
        v.w = o[d4*4+3] * inv;
        *(float4*)&ob[d4*4] = v;
    }
}

// ---------------------------------------------------------------------------
extern "C" void kernel_launch(void* const* d_in, const int* in_sizes, int n_in,
                              void* d_out, int out_size)
{
    const float* query = (const float*)d_in[0];
    const float* key   = (const float*)d_in[1];
    const float* value = (const float*)d_in[2];
    const float* Wq    = (const float*)d_in[3];
    const float* bq    = (const float*)d_in[4];
    const float* Wk    = (const float*)d_in[5];
    const float* bk    = (const float*)d_in[6];
    const float* Wv    = (const float*)d_in[7];
    const float* bv    = (const float*)d_in[8];
    const float* Wo    = (const float*)d_in[9];
    const float* bo    = (const float*)d_in[10];
    float* out = (float*)d_out;

    float *qs, *ks, *vs, *att;
    __nv_bfloat16 *ahi, *alo, *whi, *wlo;
    cudaGetSymbolAddress((void**)&qs,  g_q);
    cudaGetSymbolAddress((void**)&ks,  g_k);
    cudaGetSymbolAddress((void**)&vs,  g_v);
    cudaGetSymbolAddress((void**)&att, g_att);
    cudaGetSymbolAddress((void**)&ahi, g_ahi);
    cudaGetSymbolAddress((void**)&alo, g_alo);
    cudaGetSymbolAddress((void**)&whi, g_whi);
    cudaGetSymbolAddress((void**)&wlo, g_wlo);

    static int attr_set = 0;
    const int attn_smem = (64*64 + 64*64 + 64*128) * (int)sizeof(float);   // 64 KB
    const int gemm_smem = NSTG * STB;                                      // 96 KB
    if (!attr_set) {
        cudaFuncSetAttribute(attn_kernel,
                             cudaFuncAttributeMaxDynamicSharedMemorySize, attn_smem);
        cudaFuncSetAttribute(gemm_mma_kernel,
                             cudaFuncAttributeMaxDynamicSharedMemorySize, gemm_smem);
        attr_set = 1;
    }

    const int splitBlocks = (Bb * Ss * Dd / 4) / 256;
    dim3 tgrid(Pp / 32, Dd / 32);
    dim3 tblk(32, 8);
    dim3 ggrid(Pp / 128, (Bb * Ss) / 128);               // (8, 64)

    // Q projection
    split_kernel<<<splitBlocks, 256>>>(query, (__nv_bfloat162*)ahi, (__nv_bfloat162*)alo);
    tsplit_kernel<<<tgrid, tblk>>>(Wq, whi, wlo);
    gemm_mma_kernel<<<ggrid, 256, gemm_smem>>>(ahi, alo, whi, wlo, bq, qs, 1);
    // K projection
    split_kernel<<<splitBlocks, 256>>>(key, (__nv_bfloat162*)ahi, (__nv_bfloat162*)alo);
    tsplit_kernel<<<tgrid, tblk>>>(Wk, whi, wlo);
    gemm_mma_kernel<<<ggrid, 256, gemm_smem>>>(ahi, alo, whi, wlo, bk, ks, 1);
    // V projection
    split_kernel<<<splitBlocks, 256>>>(value, (__nv_bfloat162*)ahi, (__nv_bfloat162*)alo);
    tsplit_kernel<<<tgrid, tblk>>>(Wv, whi, wlo);
    gemm_mma_kernel<<<ggrid, 256, gemm_smem>>>(ahi, alo, whi, wlo, bv, vs, 1);

    // attention
    dim3 agrid(Ss / 128, Bb * Hh);
    attn_kernel<<<agrid, 128, attn_smem>>>(qs, ks, vs, att);

    // output projection
    split_kernel<<<splitBlocks, 256>>>(att, (__nv_bfloat162*)ahi, (__nv_bfloat162*)alo);
    tsplit_kernel<<<tgrid, tblk>>>(Wo, whi, wlo);
    gemm_mma_kernel<<<ggrid, 256, gemm_smem>>>(ahi, alo, whi, wlo, bo, out, 0);
}

// round 10
// speedup vs baseline: 2.2365x; 1.5001x over previous
#include <cuda_runtime.h>
#include <cuda_bf16.h>
#include <math.h>
#include <stdint.h>

#define Bb 4
#define Ss 2048
#define Dd 1024
#define Hh 16
#define KD 64
#define Pp 1024

// ---------------- scratch (static __device__ per allocation rules) ----------
__device__ __nv_bfloat16 g_ahi[Bb*Ss*Dd];   // activation split (reused per GEMM)
__device__ __nv_bfloat16 g_alo[Bb*Ss*Dd];
__device__ __nv_bfloat16 g_whi[Dd*Pp];      // transposed weight split [N][K]
__device__ __nv_bfloat16 g_wlo[Dd*Pp];

__device__ __nv_bfloat16 g_qhi[Bb*Hh*Ss*KD];  // [B,H,S,Kd], scale 1/8 folded
__device__ __nv_bfloat16 g_qlo[Bb*Hh*Ss*KD];
__device__ __nv_bfloat16 g_khi[Bb*Hh*Ss*KD];
__device__ __nv_bfloat16 g_klo[Bb*Hh*Ss*KD];
__device__ __nv_bfloat16 g_vhi[Bb*Hh*Ss*KD];
__device__ __nv_bfloat16 g_vlo[Bb*Hh*Ss*KD];
__device__ __nv_bfloat16 g_athi[Bb*Ss*Pp];    // attention out split [B,S,P]
__device__ __nv_bfloat16 g_atlo[Bb*Ss*Pp];

// ---------------------------------------------------------------------------
// helpers (base-target instructions only: mma.sync / ldmatrix / cp.async)
// ---------------------------------------------------------------------------
__device__ __forceinline__ uint32_t smem_u32(const void* p){
    uint32_t a;
    asm("{ .reg .u64 t; cvta.to.shared.u64 t, %1; cvt.u32.u64 %0, t; }" : "=r"(a) : "l"(p));
    return a;
}
__device__ __forceinline__ void cp16(uint32_t s, const void* g){
    asm volatile("cp.async.cg.shared.global [%0], [%1], 16;"
                 :: "r"(s), "l"(__cvta_generic_to_global(g)) : "memory");
}
__device__ __forceinline__ void ldsm4(uint32_t* d, uint32_t addr){
    asm volatile("ldmatrix.sync.aligned.m8n8.x4.shared.b16 {%0,%1,%2,%3}, [%4];"
                 : "=r"(d[0]), "=r"(d[1]), "=r"(d[2]), "=r"(d[3]) : "r"(addr));
}
__device__ __forceinline__ void ldsm4t(uint32_t* d, uint32_t addr){
    asm volatile("ldmatrix.sync.aligned.m8n8.x4.trans.shared.b16 {%0,%1,%2,%3}, [%4];"
                 : "=r"(d[0]), "=r"(d[1]), "=r"(d[2]), "=r"(d[3]) : "r"(addr));
}
__device__ __forceinline__ void mma16816(float* c, const uint32_t* a, const uint32_t* b){
    asm volatile("mma.sync.aligned.m16n8k16.row.col.f32.bf16.bf16.f32 "
                 "{%0,%1,%2,%3}, {%4,%5,%6,%7}, {%8,%9}, {%0,%1,%2,%3};"
                 : "+f"(c[0]), "+f"(c[1]), "+f"(c[2]), "+f"(c[3])
                 : "r"(a[0]), "r"(a[1]), "r"(a[2]), "r"(a[3]), "r"(b[0]), "r"(b[1]));
}
// swizzle for 64B rows (32 bf16), 16B chunk c (0..3)  -- GEMM tiles
__device__ __forceinline__ uint32_t swoff(int r, int c){
    return (uint32_t)(r * 64 + ((c ^ ((r >> 1) & 3)) << 4));
}
// swizzle for 128B rows (64 bf16), 16B chunk c (0..7)  -- attention tiles
__device__ __forceinline__ uint32_t swz128(int r, int c){
    return (uint32_t)(r * 128 + ((c ^ (r & 7)) << 4));
}
__device__ __forceinline__ uint32_t pack_bf16x2(float a, float b){
    __nv_bfloat162 t(__float2bfloat16(a), __float2bfloat16(b));
    return *reinterpret_cast<uint32_t*>(&t);
}

// ---------------------------------------------------------------------------
// split / transpose-split prep kernels
// ---------------------------------------------------------------------------
__global__ __launch_bounds__(256) void split_kernel(
    const float* __restrict__ X, __nv_bfloat162* __restrict__ hi,
    __nv_bfloat162* __restrict__ lo)
{
    int i = blockIdx.x * 256 + threadIdx.x;       // one float4 per thread
    float4 v = reinterpret_cast<const float4*>(X)[i];
    float f[4] = {v.x, v.y, v.z, v.w};
    __nv_bfloat16 h[4], l[4];
    #pragma unroll
    for (int j = 0; j < 4; j++){
        h[j] = __float2bfloat16(f[j]);
        l[j] = __float2bfloat16(f[j] - __bfloat162float(h[j]));
    }
    hi[i*2+0] = __nv_bfloat162(h[0], h[1]);
    hi[i*2+1] = __nv_bfloat162(h[2], h[3]);
    lo[i*2+0] = __nv_bfloat162(l[0], l[1]);
    lo[i*2+1] = __nv_bfloat162(l[2], l[3]);
}

// W [K=1024][N=1024] row-major -> Wt hi/lo [N][K]
__global__ __launch_bounds__(256) void tsplit_kernel(
    const float* __restrict__ W, __nv_bfloat16* __restrict__ th,
    __nv_bfloat16* __restrict__ tl)
{
    __shared__ float t[32][33];
    const int n0 = blockIdx.x * 32, k0 = blockIdx.y * 32;
    const int tx = threadIdx.x, ty = threadIdx.y;     // 32 x 8
    #pragma unroll
    for (int r = 0; r < 4; r++)
        t[ty + 8*r][tx] = W[(size_t)(k0 + ty + 8*r) * Pp + n0 + tx];
    __syncthreads();
    #pragma unroll
    for (int r = 0; r < 4; r++){
        float v = t[tx][ty + 8*r];                    // = W[k0+tx][n0+ty+8r]
        int n = n0 + ty + 8*r, k = k0 + tx;
        __nv_bfloat16 h = __float2bfloat16(v);
        th[(size_t)n * Dd + k] = h;
        tl[(size_t)n * Dd + k] = __float2bfloat16(v - __bfloat162float(h));
    }
}

// ---------------------------------------------------------------------------
// HMMA split-bf16 GEMM: 128x128 tile, BK=32, 256 threads, 3-stage cp.async.
// mode 0: C = fp32 [M][1024] (+bias)
// mode 1: split hi/lo bf16 scatter to [B,H,S,64], val=(acc+bias)*scale
// ---------------------------------------------------------------------------
#define STB  32768
#define NSTG 3
#define NKI  (Dd / 32)

__device__ __forceinline__ void stage_load(
    uint32_t sb, const __nv_bfloat16* __restrict__ Ahi,
    const __nv_bfloat16* __restrict__ Alo,
    const __nv_bfloat16* __restrict__ Bhi,
    const __nv_bfloat16* __restrict__ Blo,
    int m0, int n0, int k0, int tid)
{
    #pragma unroll
    for (int half = 0; half < 2; half++){
        int idx = tid + half * 256;
        int r = idx >> 2, c = idx & 3;
        uint32_t so = swoff(r, c);
        size_t ga = (size_t)(m0 + r) * Dd + k0 + c * 8;
        size_t gb = (size_t)(n0 + r) * Dd + k0 + c * 8;
        cp16(sb +         so, Ahi + ga);
        cp16(sb +  8192 + so, Alo + ga);
        cp16(sb + 16384 + so, Bhi + gb);
        cp16(sb + 24576 + so, Blo + gb);
    }
}

__global__ __launch_bounds__(256) void gemm_mma_kernel(
    const __nv_bfloat16* __restrict__ Ahi, const __nv_bfloat16* __restrict__ Alo,
    const __nv_bfloat16* __restrict__ Bhi, const __nv_bfloat16* __restrict__ Blo,
    const float* __restrict__ bias, float* __restrict__ Cf,
    __nv_bfloat16* __restrict__ Chi, __nv_bfloat16* __restrict__ Clo,
    float scale, int mode)
{
    extern __shared__ char dsm[];
    const uint32_t sbase = smem_u32(dsm);

    const int tid  = threadIdx.x;
    const int lane = tid & 31;
    const int wid  = tid >> 5;
    const int wm   = wid & 1;
    const int wn   = wid >> 1;
    const int n0 = blockIdx.x * 128;
    const int m0 = blockIdx.y * 128;

    float acc[4][4][4];
    #pragma unroll
    for (int i = 0; i < 4; i++)
        #pragma unroll
        for (int j = 0; j < 4; j++)
            #pragma unroll
            for (int k = 0; k < 4; k++) acc[i][j][k] = 0.f;

    stage_load(sbase,       Ahi, Alo, Bhi, Blo, m0, n0, 0,  tid);
    asm volatile("cp.async.commit_group;" ::: "memory");
    stage_load(sbase + STB, Ahi, Alo, Bhi, Blo, m0, n0, 32, tid);
    asm volatile("cp.async.commit_group;" ::: "memory");

    for (int kc = 0; kc < NKI; kc++){
        asm volatile("cp.async.wait_group 1;" ::: "memory");
        __syncthreads();

        if (kc + 2 < NKI)
            stage_load(sbase + (uint32_t)((kc + 2) % NSTG) * STB,
                       Ahi, Alo, Bhi, Blo, m0, n0, (kc + 2) * 32, tid);
        asm volatile("cp.async.commit_group;" ::: "memory");

        const uint32_t sb = sbase + (uint32_t)(kc % NSTG) * STB;
        #pragma unroll
        for (int ks = 0; ks < 2; ks++){
            uint32_t ah[4][4], al[4][4], bh[8], bl[8];
            #pragma unroll
            for (int mf = 0; mf < 4; mf++){
                int r = wm * 64 + mf * 16 + (lane & 15);
                int c = ks * 2 + (lane >> 4);
                uint32_t o = swoff(r, c);
                ldsm4(ah[mf], sb + o);
                ldsm4(al[mf], sb + 8192 + o);
            }
            #pragma unroll
            for (int p = 0; p < 2; p++){
                int r = wn * 32 + p * 16 + ((lane >> 4) << 3) + (lane & 7);
                int c = ks * 2 + ((lane >> 3) & 1);
                uint32_t o = swoff(r, c);
                ldsm4(&bh[p*4], sb + 16384 + o);
                ldsm4(&bl[p*4], sb + 24576 + o);
            }
            #pragma unroll
            for (int mf = 0; mf < 4; mf++)
                #pragma unroll
                for (int nf = 0; nf < 4; nf++){
                    mma16816(acc[mf][nf], ah[mf], &bh[nf*2]);
                    mma16816(acc[mf][nf], ah[mf], &bl[nf*2]);
                    mma16816(acc[mf][nf], al[mf], &bh[nf*2]);
                }
        }
    }

    #pragma unroll
    for (int mf = 0; mf < 4; mf++){
        #pragma unroll
        for (int nf = 0; nf < 4; nf++){
            const int col = n0 + wn * 32 + nf * 8 + (lane & 3) * 2;
            const float b0 = __ldg(&bias[col]), b1 = __ldg(&bias[col + 1]);
            #pragma unroll
            for (int half = 0; half < 2; half++){
                const int m = m0 + wm * 64 + mf * 16 + (lane >> 2) + half * 8;
                float v0 = (acc[mf][nf][half*2 + 0] + b0) * scale;
                float v1 = (acc[mf][nf][half*2 + 1] + b1) * scale;
                if (mode == 0){
                    *(float2*)&Cf[(size_t)m * Pp + col] = make_float2(v0, v1);
                } else {
                    const int b  = m >> 11;
                    const int sq = m & 2047;
                    const int h  = col >> 6;
                    const int d  = col & 63;
                    size_t idx = (((size_t)(b * Hh + h)) * Ss + sq) * KD + d;
                    __nv_bfloat16 h0 = __float2bfloat16(v0);
                    __nv_bfloat16 h1 = __float2bfloat16(v1);
                    *(__nv_bfloat162*)&Chi[idx] = __nv_bfloat162(h0, h1);
                    *(__nv_bfloat162*)&Clo[idx] = __nv_bfloat162(
                        __float2bfloat16(v0 - __bfloat162float(h0)),
                        __float2bfloat16(v1 - __bfloat162float(h1)));
                }
            }
        }
    }
}

// ---------------------------------------------------------------------------
// HMMA flash attention, causal + ALiBi, split-bf16 (3-term QK and PV).
// Block: 256 threads (8 warps), 128 q-rows (16/warp). K/V tile 64, dbl-buffered.
// smem: 2 stages x (Khi|Klo|Vhi|Vlo, 8KB each) = 64KB. Q staged via stage0.
// ---------------------------------------------------------------------------
#define AT_STAGE 32768

__device__ __forceinline__ void attn_load_kv(
    uint32_t st, const __nv_bfloat16* __restrict__ Khi,
    const __nv_bfloat16* __restrict__ Klo,
    const __nv_bfloat16* __restrict__ Vhi,
    const __nv_bfloat16* __restrict__ Vlo,
    size_t krow0, int jb, int tid)
{
    #pragma unroll
    for (int t = 0; t < 8; t++){
        int idx = tid + t * 256;          // 0..2047
        int tile = idx >> 9;              // 0..3
        int rem  = idx & 511;
        int r = rem >> 3, c = rem & 7;
        const __nv_bfloat16* base = (tile == 0) ? Khi : (tile == 1) ? Klo
                                   : (tile == 2) ? Vhi : Vlo;
        cp16(st + tile * 8192 + swz128(r, c),
             base + krow0 + (size_t)(jb + r) * KD + c * 8);
    }
}

__global__ __launch_bounds__(256) void attn_mma_kernel(
    const __nv_bfloat16* __restrict__ Qhi, const __nv_bfloat16* __restrict__ Qlo,
    const __nv_bfloat16* __restrict__ Khi, const __nv_bfloat16* __restrict__ Klo,
    const __nv_bfloat16* __restrict__ Vhi, const __nv_bfloat16* __restrict__ Vlo,
    __nv_bfloat16* __restrict__ Ohi, __nv_bfloat16* __restrict__ Olo)
{
    extern __shared__ char dsm[];
    const uint32_t sb = smem_u32(dsm);

    const int tid  = threadIdx.x;
    const int lane = tid & 31;
    const int wid  = tid >> 5;           // 0..7
    const int bx   = blockIdx.x;         // 0..15
    const int bh   = blockIdx.y;
    const int h    = bh & (Hh - 1);
    const int b    = bh >> 4;
    const int qb   = bx * 128;

    const size_t qrow0 = ((size_t)bh * Ss + qb) * KD;
    const size_t krow0 = ((size_t)bh * Ss) * KD;

    // ---- stage Q (hi 16KB | lo 16KB) into stage0, pull a-frags to regs ----
    #pragma unroll
    for (int t = 0; t < 8; t++){
        int idx = tid + t * 256;          // 0..2047
        int pre = idx >> 10;              // 0 hi, 1 lo
        int rem = idx & 1023;
        int r = rem >> 3, c = rem & 7;
        const __nv_bfloat16* base = pre ? Qlo : Qhi;
        cp16(sb + pre * 16384 + swz128(r, c), base + qrow0 + (size_t)r * KD + c * 8);
    }
    asm volatile("cp.async.commit_group;" ::: "memory");
    asm volatile("cp.async.wait_group 0;" ::: "memory");
    __syncthreads();

    uint32_t qh[4][4], ql[4][4];
    #pragma unroll
    for (int ks = 0; ks < 4; ks++){
        int r = wid * 16 + (lane & 15);
        int c = 2 * ks + (lane >> 4);
        uint32_t o = swz128(r, c);
        ldsm4(qh[ks], sb + o);
        ldsm4(ql[ks], sb + 16384 + o);
    }
    __syncthreads();   // all reads of stage0 done before K/V overwrite

    const int ntiles = 2 * bx + 2;
    attn_load_kv(sb,            Khi, Klo, Vhi, Vlo, krow0, 0,  tid);
    asm volatile("cp.async.commit_group;" ::: "memory");
    attn_load_kv(sb + AT_STAGE, Khi, Klo, Vhi, Vlo, krow0, 64, tid);
    asm volatile("cp.async.commit_group;" ::: "memory");

    float oacc[8][4];
    #pragma unroll
    for (int i = 0; i < 8; i++)
        #pragma unroll
        for (int j = 0; j < 4; j++) oacc[i][j] = 0.f;

    float mr0 = -1e30f, mr1 = -1e30f, l0 = 0.f, l1 = 0.f;
    const float slope = exp2f(-0.5f * (float)(h + 1));
    const int qi0 = qb + wid * 16 + (lane >> 2);
    const int qi1 = qi0 + 8;
    const int jcol = (lane & 3) * 2;

    for (int jt = 0; jt < ntiles; jt++){
        asm volatile("cp.async.wait_group 1;" ::: "memory");
        __syncthreads();
        const uint32_t st = sb + (uint32_t)(jt & 1) * AT_STAGE;

        // ---- S = Q K^T (3-term) ----
        float s[8][4];
        #pragma unroll
        for (int i = 0; i < 8; i++)
            #pragma unroll
            for (int j = 0; j < 4; j++) s[i][j] = 0.f;

        #pragma unroll
        for (int ks = 0; ks < 4; ks++){
            uint32_t kbh[16], kbl[16];
            #pragma unroll
            for (int p = 0; p < 4; p++){
                int r = p * 16 + ((lane >> 4) << 3) + (lane & 7);
                int c = 2 * ks + ((lane >> 3) & 1);
                uint32_t o = swz128(r, c);
                ldsm4(&kbh[p*4], st + o);
                ldsm4(&kbl[p*4], st + 8192 + o);
            }
            #pragma unroll
            for (int nf = 0; nf < 8; nf++){
                mma16816(s[nf], qh[ks], &kbh[nf*2]);
                mma16816(s[nf], qh[ks], &kbl[nf*2]);
                mma16816(s[nf], ql[ks], &kbh[nf*2]);
            }
        }

        // ---- bias + mask ----
        const int jb = jt * 64;
        const bool need_mask = (jt >= 2 * bx);
        #pragma unroll
        for (int nf = 0; nf < 8; nf++){
            const int jg0 = jb + nf * 8 + jcol;
            s[nf][0] += slope * (float)(qi0 - jg0);
            s[nf][1] += slope * (float)(qi0 - jg0 - 1);
            s[nf][2] += slope * (float)(qi1 - jg0);
            s[nf][3] += slope * (float)(qi1 - jg0 - 1);
            if (need_mask){
                if (jg0     > qi0) s[nf][0] = -1e30f;
                if (jg0 + 1 > qi0) s[nf][1] = -1e30f;
                if (jg0     > qi1) s[nf][2] = -1e30f;
                if (jg0 + 1 > qi1) s[nf][3] = -1e30f;
            }
        }

        // ---- online softmax ----
        float mx0 = -1e30f, mx1 = -1e30f;
        #pragma unroll
        for (int nf = 0; nf < 8; nf++){
            mx0 = fmaxf(mx0, fmaxf(s[nf][0], s[nf][1]));
            mx1 = fmaxf(mx1, fmaxf(s[nf][2], s[nf][3]));
        }
        mx0 = fmaxf(mx0, __shfl_xor_sync(0xffffffffu, mx0, 1));
        mx0 = fmaxf(mx0, __shfl_xor_sync(0xffffffffu, mx0, 2));
        mx1 = fmaxf(mx1, __shfl_xor_sync(0xffffffffu, mx1, 1));
        mx1 = fmaxf(mx1, __shfl_xor_sync(0xffffffffu, mx1, 2));

        const float mn0 = fmaxf(mr0, mx0);
        const float mn1 = fmaxf(mr1, mx1);
        const float c0 = __expf(mr0 - mn0);
        const float c1 = __expf(mr1 - mn1);
        l0 *= c0; l1 *= c1;
        #pragma unroll
        for (int df = 0; df < 8; df++){
            oacc[df][0] *= c0; oacc[df][1] *= c0;
            oacc[df][2] *= c1; oacc[df][3] *= c1;
        }
        mr0 = mn0; mr1 = mn1;

        // ---- p = exp, split, repack into PV A-frags ----
        uint32_t pah[4][4], pal[4][4];
        #pragma unroll
        for (int nf = 0; nf < 8; nf++){
            float p0 = __expf(s[nf][0] - mn0);
            float p1 = __expf(s[nf][1] - mn0);
            float p2 = __expf(s[nf][2] - mn1);
            float p3 = __expf(s[nf][3] - mn1);
            l0 += p0 + p1; l1 += p2 + p3;
            __nv_bfloat16 h0 = __float2bfloat16(p0), h1 = __float2bfloat16(p1);
            __nv_bfloat16 h2 = __float2bfloat16(p2), h3 = __float2bfloat16(p3);
            const int ks  = nf >> 1;
            const int pos = (nf & 1) * 2;
            __nv_bfloat162 th01(h0, h1), th23(h2, h3);
            pah[ks][pos + 0] = *reinterpret_cast<uint32_t*>(&th01);
            pah[ks][pos + 1] = *reinterpret_cast<uint32_t*>(&th23);
            pal[ks][pos + 0] = pack_bf16x2(p0 - __bfloat162float(h0),
                                           p1 - __bfloat162float(h1));
            pal[ks][pos + 1] = pack_bf16x2(p2 - __bfloat162float(h2),
                                           p3 - __bfloat162float(h3));
        }

        // ---- O += P V (3-term), V via ldmatrix.trans ----
        #pragma unroll
        for (int ks = 0; ks < 4; ks++){
            uint32_t vbh[16], vbl[16];
            #pragma unroll
            for (int g = 0; g < 4; g++){
                int r = ks * 16 + ((lane >> 3) & 1) * 8 + (lane & 7);
                int c = 2 * g + (lane >> 4);
                uint32_t o = swz128(r, c);
                ldsm4t(&vbh[g*4], st + 16384 + o);
                ldsm4t(&vbl[g*4], st + 24576 + o);
            }
            #pragma unroll
            for (int df = 0; df < 8; df++){
                mma16816(oacc[df], pah[ks], &vbh[df*2]);
                mma16816(oacc[df], pah[ks], &vbl[df*2]);
                mma16816(oacc[df], pal[ks], &vbh[df*2]);
            }
        }

        __syncthreads();   // stage fully consumed before refill
        if (jt + 2 < ntiles)
            attn_load_kv(sb + (uint32_t)(jt & 1) * AT_STAGE,
                         Khi, Klo, Vhi, Vlo, krow0, (jt + 2) * 64, tid);
        asm volatile("cp.async.commit_group;" ::: "memory");
    }

    // ---- epilogue: normalize, split hi/lo bf16, store [B,S,P] ----
    l0 += __shfl_xor_sync(0xffffffffu, l0, 1);
    l0 += __shfl_xor_sync(0xffffffffu, l0, 2);
    l1 += __shfl_xor_sync(0xffffffffu, l1, 1);
    l1 += __shfl_xor_sync(0xffffffffu, l1, 2);
    const float inv0 = 1.f / l0, inv1 = 1.f / l1;

    const size_t orow0 = ((size_t)(b * Ss + qi0)) * Pp + h * KD;
    const size_t orow1 = ((size_t)(b * Ss + qi1)) * Pp + h * KD;
    #pragma unroll
    for (int df = 0; df < 8; df++){
        const int d = df * 8 + jcol;
        float v0 = oacc[df][0] * inv0, v1 = oacc[df][1] * inv0;
        float v2 = oacc[df][2] * inv1, v3 = oacc[df][3] * inv1;
        __nv_bfloat16 h0 = __float2bfloat16(v0), h1 = __float2bfloat16(v1);
        __nv_bfloat16 h2 = __float2bfloat16(v2), h3 = __float2bfloat16(v3);
        *(__nv_bfloat162*)&Ohi[orow0 + d] = __nv_bfloat162(h0, h1);
        *(__nv_bfloat162*)&Ohi[orow1 + d] = __nv_bfloat162(h2, h3);
        *(__nv_bfloat162*)&Olo[orow0 + d] = __nv_bfloat162(
            __float2bfloat16(v0 - __bfloat162float(h0)),
            __float2bfloat16(v1 - __bfloat162float(h1)));
        *(__nv_bfloat162*)&Olo[orow1 + d] = __nv_bfloat162(
            __float2bfloat16(v2 - __bfloat162float(h2)),
            __float2bfloat16(v3 - __bfloat162float(h3)));
    }
}

// ---------------------------------------------------------------------------
extern "C" void kernel_launch(void* const* d_in, const int* in_sizes, int n_in,
                              void* d_out, int out_size)
{
    const float* query = (const float*)d_in[0];
    const float* key   = (const float*)d_in[1];
    const float* value = (const float*)d_in[2];
    const float* Wq    = (const float*)d_in[3];
    const float* bq    = (const float*)d_in[4];
    const float* Wk    = (const float*)d_in[5];
    const float* bk    = (const float*)d_in[6];
    const float* Wv    = (const float*)d_in[7];
    const float* bv    = (const float*)d_in[8];
    const float* Wo    = (const float*)d_in[9];
    const float* bo    = (const float*)d_in[10];
    float* out = (float*)d_out;

    __nv_bfloat16 *ahi, *alo, *whi, *wlo;
    __nv_bfloat16 *qhi, *qlo, *khi, *klo, *vhi, *vlo, *athi, *atlo;
    cudaGetSymbolAddress((void**)&ahi, g_ahi);
    cudaGetSymbolAddress((void**)&alo, g_alo);
    cudaGetSymbolAddress((void**)&whi, g_whi);
    cudaGetSymbolAddress((void**)&wlo, g_wlo);
    cudaGetSymbolAddress((void**)&qhi, g_qhi);
    cudaGetSymbolAddress((void**)&qlo, g_qlo);
    cudaGetSymbolAddress((void**)&khi, g_khi);
    cudaGetSymbolAddress((void**)&klo, g_klo);
    cudaGetSymbolAddress((void**)&vhi, g_vhi);
    cudaGetSymbolAddress((void**)&vlo, g_vlo);
    cudaGetSymbolAddress((void**)&athi, g_athi);
    cudaGetSymbolAddress((void**)&atlo, g_atlo);

    static int attr_set = 0;
    const int gemm_smem = NSTG * STB;        // 96 KB
    const int attn_smem = 2 * AT_STAGE;      // 64 KB
    if (!attr_set) {
        cudaFuncSetAttribute(gemm_mma_kernel,
                             cudaFuncAttributeMaxDynamicSharedMemorySize, gemm_smem);
        cudaFuncSetAttribute(attn_mma_kernel,
                             cudaFuncAttributeMaxDynamicSharedMemorySize, attn_smem);
        attr_set = 1;
    }

    const int splitBlocks = (Bb * Ss * Dd / 4) / 256;
    dim3 tgrid(Pp / 32, Dd / 32);
    dim3 tblk(32, 8);
    dim3 ggrid(Pp / 128, (Bb * Ss) / 128);   // (8, 64)

    // Q projection (scale 1/8 folded into split output)
    split_kernel<<<splitBlocks, 256>>>(query, (__nv_bfloat162*)ahi, (__nv_bfloat162*)alo);
    tsplit_kernel<<<tgrid, tblk>>>(Wq, whi, wlo);
    gemm_mma_kernel<<<ggrid, 256, gemm_smem>>>(ahi, alo, whi, wlo, bq,
                                               nullptr, qhi, qlo, 0.125f, 1);
    // K projection
    split_kernel<<<splitBlocks, 256>>>(key, (__nv_bfloat162*)ahi, (__nv_bfloat162*)alo);
    tsplit_kernel<<<tgrid, tblk>>>(Wk, whi, wlo);
    gemm_mma_kernel<<<ggrid, 256, gemm_smem>>>(ahi, alo, whi, wlo, bk,
                                               nullptr, khi, klo, 1.0f, 1);
    // V projection
    split_kernel<<<splitBlocks, 256>>>(value, (__nv_bfloat162*)ahi, (__nv_bfloat162*)alo);
    tsplit_kernel<<<tgrid, tblk>>>(Wv, whi, wlo);
    gemm_mma_kernel<<<ggrid, 256, gemm_smem>>>(ahi, alo, whi, wlo, bv,
                                               nullptr, vhi, vlo, 1.0f, 1);

    // attention (HMMA, split output feeds final GEMM directly)
    dim3 agrid(Ss / 128, Bb * Hh);
    attn_mma_kernel<<<agrid, 256, attn_smem>>>(qhi, qlo, khi, klo, vhi, vlo,
                                               athi, atlo);

    // output projection
    tsplit_kernel<<<tgrid, tblk>>>(Wo, whi, wlo);
    gemm_mma_kernel<<<ggrid, 256, gemm_smem>>>(athi, atlo, whi, wlo, bo,
                                               out, nullptr, nullptr, 1.0f, 0);
}

// round 14
// speedup vs baseline: 3.5173x; 1.5727x over previous
#include <cuda_runtime.h>
#include <cuda_bf16.h>
#include <math.h>
#include <stdint.h>

#define Bb 4
#define Ss 2048
#define Dd 1024
#define Hh 16
#define KD 64
#define Pp 1024
#define Mm (Bb*Ss)          // 8192

// ---------------- scratch (static __device__ per allocation rules) ----------
__device__ __nv_bfloat16 g_a3hi[3*Mm*Dd];     // q|k|v activation splits
__device__ __nv_bfloat16 g_a3lo[3*Mm*Dd];
__device__ __nv_bfloat16 g_w3hi[3*Dd*Pp];     // Wq|Wk|Wv transposed splits [N][K]
__device__ __nv_bfloat16 g_w3lo[3*Dd*Pp];
__device__ __nv_bfloat16 g_wohi[Dd*Pp];       // Wo transposed split
__device__ __nv_bfloat16 g_wolo[Dd*Pp];

__device__ __nv_bfloat16 g_qkvhi[3*Bb*Hh*Ss*KD];  // q|k|v [B,H,S,Kd] (q scaled 1/8)
__device__ __nv_bfloat16 g_qkvlo[3*Bb*Hh*Ss*KD];
__device__ __nv_bfloat16 g_athi[Bb*Ss*Pp];        // attention out split [B,S,P]
__device__ __nv_bfloat16 g_atlo[Bb*Ss*Pp];

// ---------------------------------------------------------------------------
// helpers (base-target instructions only: mma.sync / ldmatrix / cp.async)
// ---------------------------------------------------------------------------
__device__ __forceinline__ uint32_t smem_u32(const void* p){
    uint32_t a;
    asm("{ .reg .u64 t; cvta.to.shared.u64 t, %1; cvt.u32.u64 %0, t; }" : "=r"(a) : "l"(p));
    return a;
}
__device__ __forceinline__ void cp16(uint32_t s, const void* g){
    asm volatile("cp.async.cg.shared.global [%0], [%1], 16;"
                 :: "r"(s), "l"(__cvta_generic_to_global(g)) : "memory");
}
__device__ __forceinline__ void ldsm4(uint32_t* d, uint32_t addr){
    asm volatile("ldmatrix.sync.aligned.m8n8.x4.shared.b16 {%0,%1,%2,%3}, [%4];"
                 : "=r"(d[0]), "=r"(d[1]), "=r"(d[2]), "=r"(d[3]) : "r"(addr));
}
__device__ __forceinline__ void ldsm4t(uint32_t* d, uint32_t addr){
    asm volatile("ldmatrix.sync.aligned.m8n8.x4.trans.shared.b16 {%0,%1,%2,%3}, [%4];"
                 : "=r"(d[0]), "=r"(d[1]), "=r"(d[2]), "=r"(d[3]) : "r"(addr));
}
__device__ __forceinline__ void mma16816(float* c, const uint32_t* a, const uint32_t* b){
    asm volatile("mma.sync.aligned.m16n8k16.row.col.f32.bf16.bf16.f32 "
                 "{%0,%1,%2,%3}, {%4,%5,%6,%7}, {%8,%9}, {%0,%1,%2,%3};"
                 : "+f"(c[0]), "+f"(c[1]), "+f"(c[2]), "+f"(c[3])
                 : "r"(a[0]), "r"(a[1]), "r"(a[2]), "r"(a[3]), "r"(b[0]), "r"(b[1]));
}
// swizzle for 128B rows (64 bf16), 16B chunk c (0..7)
__device__ __forceinline__ uint32_t swz128(int r, int c){
    return (uint32_t)(r * 128 + ((c ^ (r & 7)) << 4));
}
__device__ __forceinline__ uint32_t pack_bf16x2(float a, float b){
    __nv_bfloat162 t(__float2bfloat16(a), __float2bfloat16(b));
    return *reinterpret_cast<uint32_t*>(&t);
}

// ---------------------------------------------------------------------------
// fused split of q/k/v activations  (grid = 3 * 8192)
// ---------------------------------------------------------------------------
__global__ __launch_bounds__(256) void split3_kernel(
    const float* __restrict__ Xq, const float* __restrict__ Xk,
    const float* __restrict__ Xv,
    __nv_bfloat162* __restrict__ hi, __nv_bfloat162* __restrict__ lo)
{
    const int bx  = blockIdx.x;
    const int seg = bx >> 13;                       // 8192 blocks per segment
    const int i   = (bx & 8191) * 256 + threadIdx.x; // float4 index in segment
    const float* X = (seg == 0) ? Xq : (seg == 1) ? Xk : Xv;
    float4 v = reinterpret_cast<const float4*>(X)[i];
    float f[4] = {v.x, v.y, v.z, v.w};
    __nv_bfloat16 h[4], l[4];
    #pragma unroll
    for (int j = 0; j < 4; j++){
        h[j] = __float2bfloat16(f[j]);
        l[j] = __float2bfloat16(f[j] - __bfloat162float(h[j]));
    }
    size_t o = (size_t)seg * (Mm * Dd / 2) + (size_t)i * 2;
    hi[o+0] = __nv_bfloat162(h[0], h[1]);
    hi[o+1] = __nv_bfloat162(h[2], h[3]);
    lo[o+0] = __nv_bfloat162(l[0], l[1]);
    lo[o+1] = __nv_bfloat162(l[2], l[3]);
}

// W [K=1024][N=1024] row-major -> Wt hi/lo [N][K]  (dst pre-offset by caller)
__global__ __launch_bounds__(256) void tsplit_kernel(
    const float* __restrict__ W, __nv_bfloat16* __restrict__ th,
    __nv_bfloat16* __restrict__ tl)
{
    __shared__ float t[32][33];
    const int n0 = blockIdx.x * 32, k0 = blockIdx.y * 32;
    const int tx = threadIdx.x, ty = threadIdx.y;     // 32 x 8
    #pragma unroll
    for (int r = 0; r < 4; r++)
        t[ty + 8*r][tx] = W[(size_t)(k0 + ty + 8*r) * Pp + n0 + tx];
    __syncthreads();
    #pragma unroll
    for (int r = 0; r < 4; r++){
        float v = t[tx][ty + 8*r];
        int n = n0 + ty + 8*r, k = k0 + tx;
        __nv_bfloat16 h = __float2bfloat16(v);
        th[(size_t)n * Dd + k] = h;
        tl[(size_t)n * Dd + k] = __float2bfloat16(v - __bfloat162float(h));
    }
}

// ---------------------------------------------------------------------------
// HMMA split-bf16 GEMM: 128x128 tile, BK=64, 256 threads, 3-stage cp.async,
// register-level fragment double-buffering.
// mode 1 (fused QKV): wsel = blockIdx.x>>3 picks A/W/bias segment; split-bf16
//   scatter to g_qkvhi/lo [seg][B,H,S,64], scale 1/8 on seg 0.
// mode 0 (out proj):   fp32 output [M][1024] + bias.
// ---------------------------------------------------------------------------
#define STB   65536            // 4 tiles x (128 x 64 bf16 = 16KB)
#define NSTG  3
#define NKI   (Dd / 64)        // 16

__device__ __forceinline__ void stage_load(
    uint32_t sb, const __nv_bfloat16* __restrict__ Ahi,
    const __nv_bfloat16* __restrict__ Alo,
    const __nv_bfloat16* __restrict__ Whi,
    const __nv_bfloat16* __restrict__ Wlo,
    int m0, int n0, int k0, int tid)
{
    const __nv_bfloat16* bases[4] = {Ahi, Alo, Whi, Wlo};
    #pragma unroll
    for (int tile = 0; tile < 4; tile++){
        const __nv_bfloat16* base = bases[tile];
        const int row0 = (tile < 2) ? m0 : n0;
        #pragma unroll
        for (int t = 0; t < 4; t++){
            int idx = tid + t * 256;          // 0..1023
            int r = idx >> 3, c = idx & 7;
            cp16(sb + tile * 16384 + swz128(r, c),
                 base + (size_t)(row0 + r) * Dd + k0 + c * 8);
        }
    }
}

__global__ __launch_bounds__(256) void gemm_mma_kernel(
    const __nv_bfloat16* __restrict__ Ahi, const __nv_bfloat16* __restrict__ Alo,
    const __nv_bfloat16* __restrict__ Whi, const __nv_bfloat16* __restrict__ Wlo,
    const float* __restrict__ b0p, const float* __restrict__ b1p,
    const float* __restrict__ b2p,
    float* __restrict__ Cf, __nv_bfloat16* __restrict__ Chi,
    __nv_bfloat16* __restrict__ Clo, int mode)
{
    extern __shared__ char dsm[];
    const uint32_t sbase = smem_u32(dsm);

    const int tid  = threadIdx.x;
    const int lane = tid & 31;
    const int wid  = tid >> 5;
    const int wm   = wid & 1;            // 0..1  (64 rows)
    const int wn   = wid >> 1;           // 0..3  (32 cols)

    const int wsel = (mode == 1) ? (blockIdx.x >> 3) : 0;
    const int n0   = blockIdx.x * 128;            // row into W (possibly 3-seg)
    const int m0   = blockIdx.y * 128;
    const int coln = n0 & 1023;                   // column within projection
    const float* bias = (wsel == 0) ? b0p : (wsel == 1) ? b1p : b2p;
    const float scale = (mode == 1 && wsel == 0) ? 0.125f : 1.0f;
    const __nv_bfloat16* Ah = Ahi + (size_t)wsel * Mm * Dd;
    const __nv_bfloat16* Al = Alo + (size_t)wsel * Mm * Dd;

    float acc[4][4][4];
    #pragma unroll
    for (int i = 0; i < 4; i++)
        #pragma unroll
        for (int j = 0; j < 4; j++)
            #pragma unroll
            for (int k = 0; k < 4; k++) acc[i][j][k] = 0.f;

    stage_load(sbase,       Ah, Al, Whi, Wlo, m0, n0, 0,  tid);
    asm volatile("cp.async.commit_group;" ::: "memory");
    stage_load(sbase + STB, Ah, Al, Whi, Wlo, m0, n0, 64, tid);
    asm volatile("cp.async.commit_group;" ::: "memory");

    uint32_t ah[2][4][4], al[2][4][4], bh[2][8], bl[2][8];

    for (int kc = 0; kc < NKI; kc++){
        asm volatile("cp.async.wait_group 1;" ::: "memory");
        __syncthreads();

        if (kc + 2 < NKI)
            stage_load(sbase + (uint32_t)((kc + 2) % NSTG) * STB,
                       Ah, Al, Whi, Wlo, m0, n0, (kc + 2) * 64, tid);
        asm volatile("cp.async.commit_group;" ::: "memory");

        const uint32_t sb = sbase + (uint32_t)(kc % NSTG) * STB;

        // ---- fragment loads for ks with double buffering ----
        #define LOAD_FRAGS(ks, buf)                                            \
        {                                                                      \
            _Pragma("unroll")                                                  \
            for (int mf = 0; mf < 4; mf++){                                    \
                int r = wm * 64 + mf * 16 + (lane & 15);                       \
                int c = (ks) * 2 + (lane >> 4);                                \
                uint32_t o = swz128(r, c);                                     \
                ldsm4(ah[buf][mf], sb + o);                                    \
                ldsm4(al[buf][mf], sb + 16384 + o);                            \
            }                                                                  \
            _Pragma("unroll")                                                  \
            for (int p = 0; p < 2; p++){                                       \
                int r = wn * 32 + p * 16 + ((lane >> 4) << 3) + (lane & 7);    \
                int c = (ks) * 2 + ((lane >> 3) & 1);                          \
                uint32_t o = swz128(r, c);                                     \
                ldsm4(&bh[buf][p*4], sb + 32768 + o);                          \
                ldsm4(&bl[buf][p*4], sb + 49152 + o);                          \
            }                                                                  \
        }

        LOAD_FRAGS(0, 0)
        #pragma unroll
        for (int ks = 0; ks < 4; ks++){
            const int cur = ks & 1;
            if (ks < 3) LOAD_FRAGS(ks + 1, cur ^ 1)
            #pragma unroll
            for (int mf = 0; mf < 4; mf++)
                #pragma unroll
                for (int nf = 0; nf < 4; nf++){
                    mma16816(acc[mf][nf], ah[cur][mf], &bh[cur][nf*2]);
                    mma16816(acc[mf][nf], ah[cur][mf], &bl[cur][nf*2]);
                    mma16816(acc[mf][nf], al[cur][mf], &bh[cur][nf*2]);
                }
        }
        #undef LOAD_FRAGS
        __syncthreads();
    }

    #pragma unroll
    for (int mf = 0; mf < 4; mf++){
        #pragma unroll
        for (int nf = 0; nf < 4; nf++){
            const int col = coln + wn * 32 + nf * 8 + (lane & 3) * 2;
            const float bv0 = __ldg(&bias[col]), bv1 = __ldg(&bias[col + 1]);
            #pragma unroll
            for (int half = 0; half < 2; half++){
                const int m = m0 + wm * 64 + mf * 16 + (lane >> 2) + half * 8;
                float v0 = (acc[mf][nf][half*2 + 0] + bv0) * scale;
                float v1 = (acc[mf][nf][half*2 + 1] + bv1) * scale;
                if (mode == 0){
                    *(float2*)&Cf[(size_t)m * Pp + col] = make_float2(v0, v1);
                } else {
                    const int b  = m >> 11;
                    const int sq = m & 2047;
                    const int h  = col >> 6;
                    const int d  = col & 63;
                    size_t idx = (size_t)wsel * (Bb*Hh*Ss*KD)
                               + (((size_t)(b * Hh + h)) * Ss + sq) * KD + d;
                    __nv_bfloat16 h0 = __float2bfloat16(v0);
                    __nv_bfloat16 h1 = __float2bfloat16(v1);
                    *(__nv_bfloat162*)&Chi[idx] = __nv_bfloat162(h0, h1);
                    *(__nv_bfloat162*)&Clo[idx] = __nv_bfloat162(
                        __float2bfloat16(v0 - __bfloat162float(h0)),
                        __float2bfloat16(v1 - __bfloat162float(h1)));
                }
            }
        }
    }
}

// ---------------------------------------------------------------------------
// HMMA flash attention, causal + ALiBi, split-bf16 (unchanged from R9 WIN).
// ---------------------------------------------------------------------------
#define AT_STAGE 32768

__device__ __forceinline__ void attn_load_kv(
    uint32_t st, const __nv_bfloat16* __restrict__ Khi,
    const __nv_bfloat16* __restrict__ Klo,
    const __nv_bfloat16* __restrict__ Vhi,
    const __nv_bfloat16* __restrict__ Vlo,
    size_t krow0, int jb, int tid)
{
    #pragma unroll
    for (int t = 0; t < 8; t++){
        int idx = tid + t * 256;
        int tile = idx >> 9;
        int rem  = idx & 511;
        int r = rem >> 3, c = rem & 7;
        const __nv_bfloat16* base = (tile == 0) ? Khi : (tile == 1) ? Klo
                                   : (tile == 2) ? Vhi : Vlo;
        cp16(st + tile * 8192 + swz128(r, c) % 8192 + (swz128(r, c) / 8192) * 0,
             base + krow0 + (size_t)(jb + r) * KD + c * 8);
    }
}

__global__ __launch_bounds__(256) void attn_mma_kernel(
    const __nv_bfloat16* __restrict__ Qhi, const __nv_bfloat16* __restrict__ Qlo,
    const __nv_bfloat16* __restrict__ Khi, const __nv_bfloat16* __restrict__ Klo,
    const __nv_bfloat16* __restrict__ Vhi, const __nv_bfloat16* __restrict__ Vlo,
    __nv_bfloat16* __restrict__ Ohi, __nv_bfloat16* __restrict__ Olo)
{
    extern __shared__ char dsm[];
    const uint32_t sb = smem_u32(dsm);

    const int tid  = threadIdx.x;
    const int lane = tid & 31;
    const int wid  = tid >> 5;
    const int bx   = blockIdx.x;
    const int bh   = blockIdx.y;
    const int h    = bh & (Hh - 1);
    const int b    = bh >> 4;
    const int qb   = bx * 128;

    const size_t qrow0 = ((size_t)bh * Ss + qb) * KD;
    const size_t krow0 = ((size_t)bh * Ss) * KD;

    #pragma unroll
    for (int t = 0; t < 8; t++){
        int idx = tid + t * 256;
        int pre = idx >> 10;
        int rem = idx & 1023;
        int r = rem >> 3, c = rem & 7;
        const __nv_bfloat16* base = pre ? Qlo : Qhi;
        cp16(sb + pre * 16384 + swz128(r, c), base + qrow0 + (size_t)r * KD + c * 8);
    }
    asm volatile("cp.async.commit_group;" ::: "memory");
    asm volatile("cp.async.wait_group 0;" ::: "memory");
    __syncthreads();

    uint32_t qh[4][4], ql[4][4];
    #pragma unroll
    for (int ks = 0; ks < 4; ks++){
        int r = wid * 16 + (lane & 15);
        int c = 2 * ks + (lane >> 4);
        uint32_t o = swz128(r, c);
        ldsm4(qh[ks], sb + o);
        ldsm4(ql[ks], sb + 16384 + o);
    }
    __syncthreads();

    const int ntiles = 2 * bx + 2;
    attn_load_kv(sb,            Khi, Klo, Vhi, Vlo, krow0, 0,  tid);
    asm volatile("cp.async.commit_group;" ::: "memory");
    attn_load_kv(sb + AT_STAGE, Khi, Klo, Vhi, Vlo, krow0, 64, tid);
    asm volatile("cp.async.commit_group;" ::: "memory");

    float oacc[8][4];
    #pragma unroll
    for (int i = 0; i < 8; i++)
        #pragma unroll
        for (int j = 0; j < 4; j++) oacc[i][j] = 0.f;

    float mr0 = -1e30f, mr1 = -1e30f, l0 = 0.f, l1 = 0.f;
    const float slope = exp2f(-0.5f * (float)(h + 1));
    const int qi0 = qb + wid * 16 + (lane >> 2);
    const int qi1 = qi0 + 8;
    const int jcol = (lane & 3) * 2;

    for (int jt = 0; jt < ntiles; jt++){
        asm volatile("cp.async.wait_group 1;" ::: "memory");
        __syncthreads();
        const uint32_t st = sb + (uint32_t)(jt & 1) * AT_STAGE;

        float s[8][4];
        #pragma unroll
        for (int i = 0; i < 8; i++)
            #pragma unroll
            for (int j = 0; j < 4; j++) s[i][j] = 0.f;

        #pragma unroll
        for (int ks = 0; ks < 4; ks++){
            uint32_t kbh[16], kbl[16];
            #pragma unroll
            for (int p = 0; p < 4; p++){
                int r = p * 16 + ((lane >> 4) << 3) + (lane & 7);
                int c = 2 * ks + ((lane >> 3) & 1);
                uint32_t o = swz128(r, c);
                ldsm4(&kbh[p*4], st + o);
                ldsm4(&kbl[p*4], st + 8192 + o);
            }
            #pragma unroll
            for (int nf = 0; nf < 8; nf++){
                mma16816(s[nf], qh[ks], &kbh[nf*2]);
                mma16816(s[nf], qh[ks], &kbl[nf*2]);
                mma16816(s[nf], ql[ks], &kbh[nf*2]);
            }
        }

        const int jb = jt * 64;
        const bool need_mask = (jt >= 2 * bx);
        #pragma unroll
        for (int nf = 0; nf < 8; nf++){
            const int jg0 = jb + nf * 8 + jcol;
            s[nf][0] += slope * (float)(qi0 - jg0);
            s[nf][1] += slope * (float)(qi0 - jg0 - 1);
            s[nf][2] += slope * (float)(qi1 - jg0);
            s[nf][3] += slope * (float)(qi1 - jg0 - 1);
            if (need_mask){
                if (jg0     > qi0) s[nf][0] = -1e30f;
                if (jg0 + 1 > qi0) s[nf][1] = -1e30f;
                if (jg0     > qi1) s[nf][2] = -1e30f;
                if (jg0 + 1 > qi1) s[nf][3] = -1e30f;
            }
        }

        float mx0 = -1e30f, mx1 = -1e30f;
        #pragma unroll
        for (int nf = 0; nf < 8; nf++){
            mx0 = fmaxf(mx0, fmaxf(s[nf][0], s[nf][1]));
            mx1 = fmaxf(mx1, fmaxf(s[nf][2], s[nf][3]));
        }
        mx0 = fmaxf(mx0, __shfl_xor_sync(0xffffffffu, mx0, 1));
        mx0 = fmaxf(mx0, __shfl_xor_sync(0xffffffffu, mx0, 2));
        mx1 = fmaxf(mx1, __shfl_xor_sync(0xffffffffu, mx1, 1));
        mx1 = fmaxf(mx1, __shfl_xor_sync(0xffffffffu, mx1, 2));

        const float mn0 = fmaxf(mr0, mx0);
        const float mn1 = fmaxf(mr1, mx1);
        const float c0 = __expf(mr0 - mn0);
        const float c1 = __expf(mr1 - mn1);
        l0 *= c0; l1 *= c1;
        #pragma unroll
        for (int df = 0; df < 8; df++){
            oacc[df][0] *= c0; oacc[df][1] *= c0;
            oacc[df][2] *= c1; oacc[df][3] *= c1;
        }
        mr0 = mn0; mr1 = mn1;

        uint32_t pah[4][4], pal[4][4];
        #pragma unroll
        for (int nf = 0; nf < 8; nf++){
            float p0 = __expf(s[nf][0] - mn0);
            float p1 = __expf(s[nf][1] - mn0);
            float p2 = __expf(s[nf][2] - mn1);
            float p3 = __expf(s[nf][3] - mn1);
            l0 += p0 + p1; l1 += p2 + p3;
            __nv_bfloat16 h0 = __float2bfloat16(p0), h1 = __float2bfloat16(p1);
            __nv_bfloat16 h2 = __float2bfloat16(p2), h3 = __float2bfloat16(p3);
            const int ks  = nf >> 1;
            const int pos = (nf & 1) * 2;
            __nv_bfloat162 th01(h0, h1), th23(h2, h3);
            pah[ks][pos + 0] = *reinterpret_cast<uint32_t*>(&th01);
            pah[ks][pos + 1] = *reinterpret_cast<uint32_t*>(&th23);
            pal[ks][pos + 0] = pack_bf16x2(p0 - __bfloat162float(h0),
                                           p1 - __bfloat162float(h1));
            pal[ks][pos + 1] = pack_bf16x2(p2 - __bfloat162float(h2),
                                           p3 - __bfloat162float(h3));
        }

        #pragma unroll
        for (int ks = 0; ks < 4; ks++){
            uint32_t vbh[16], vbl[16];
            #pragma unroll
            for (int g = 0; g < 4; g++){
                int r = ks * 16 + ((lane >> 3) & 1) * 8 + (lane & 7);
                int c = 2 * g + (lane >> 4);
                uint32_t o = swz128(r, c);
                ldsm4t(&vbh[g*4], st + 16384 + o);
                ldsm4t(&vbl[g*4], st + 24576 + o);
            }
            #pragma unroll
            for (int df = 0; df < 8; df++){
                mma16816(oacc[df], pah[ks], &vbh[df*2]);
                mma16816(oacc[df], pah[ks], &vbl[df*2]);
                mma16816(oacc[df], pal[ks], &vbh[df*2]);
            }
        }

        __syncthreads();
        if (jt + 2 < ntiles)
            attn_load_kv(sb + (uint32_t)(jt & 1) * AT_STAGE,
                         Khi, Klo, Vhi, Vlo, krow0, (jt + 2) * 64, tid);
        asm volatile("cp.async.commit_group;" ::: "memory");
    }

    l0 += __shfl_xor_sync(0xffffffffu, l0, 1);
    l0 += __shfl_xor_sync(0xffffffffu, l0, 2);
    l1 += __shfl_xor_sync(0xffffffffu, l1, 1);
    l1 += __shfl_xor_sync(0xffffffffu, l1, 2);
    const float inv0 = 1.f / l0, inv1 = 1.f / l1;

    const size_t orow0 = ((size_t)(b * Ss + qi0)) * Pp + h * KD;
    const size_t orow1 = ((size_t)(b * Ss + qi1)) * Pp + h * KD;
    #pragma unroll
    for (int df = 0; df < 8; df++){
        const int d = df * 8 + jcol;
        float v0 = oacc[df][0] * inv0, v1 = oacc[df][1] * inv0;
        float v2 = oacc[df][2] * inv1, v3 = oacc[df][3] * inv1;
        __nv_bfloat16 h0 = __float2bfloat16(v0), h1 = __float2bfloat16(v1);
        __nv_bfloat16 h2 = __float2bfloat16(v2), h3 = __float2bfloat16(v3);
        *(__nv_bfloat162*)&Ohi[orow0 + d] = __nv_bfloat162(h0, h1);
        *(__nv_bfloat162*)&Ohi[orow1 + d] = __nv_bfloat162(h2, h3);
        *(__nv_bfloat162*)&Olo[orow0 + d] = __nv_bfloat162(
            __float2bfloat16(v0 - __bfloat162float(h0)),
            __float2bfloat16(v1 - __bfloat162float(h1)));
        *(__nv_bfloat162*)&Olo[orow1 + d] = __nv_bfloat162(
            __float2bfloat16(v2 - __bfloat162float(h2)),
            __float2bfloat16(v3 - __bfloat162float(h3)));
    }
}

// ---------------------------------------------------------------------------
extern "C" void kernel_launch(void* const* d_in, const int* in_sizes, int n_in,
                              void* d_out, int out_size)
{
    const float* query = (const float*)d_in[0];
    const float* key   = (const float*)d_in[1];
    const float* value = (const float*)d_in[2];
    const float* Wq    = (const float*)d_in[3];
    const float* bq    = (const float*)d_in[4];
    const float* Wk    = (const float*)d_in[5];
    const float* bk    = (const float*)d_in[6];
    const float* Wv    = (const float*)d_in[7];
    const float* bv    = (const float*)d_in[8];
    const float* Wo    = (const float*)d_in[9];
    const float* bo    = (const float*)d_in[10];
    float* out = (float*)d_out;

    __nv_bfloat16 *a3hi, *a3lo, *w3hi, *w3lo, *wohi, *wolo;
    __nv_bfloat16 *qkvhi, *qkvlo, *athi, *atlo;
    cudaGetSymbolAddress((void**)&a3hi,  g_a3hi);
    cudaGetSymbolAddress((void**)&a3lo,  g_a3lo);
    cudaGetSymbolAddress((void**)&w3hi,  g_w3hi);
    cudaGetSymbolAddress((void**)&w3lo,  g_w3lo);
    cudaGetSymbolAddress((void**)&wohi,  g_wohi);
    cudaGetSymbolAddress((void**)&wolo,  g_wolo);
    cudaGetSymbolAddress((void**)&qkvhi, g_qkvhi);
    cudaGetSymbolAddress((void**)&qkvlo, g_qkvlo);
    cudaGetSymbolAddress((void**)&athi,  g_athi);
    cudaGetSymbolAddress((void**)&atlo,  g_atlo);

    static int attr_set = 0;
    const int gemm_smem = NSTG * STB;        // 192 KB
    const int attn_smem = 2 * AT_STAGE;      // 64 KB
    if (!attr_set) {
        cudaFuncSetAttribute(gemm_mma_kernel,
                             cudaFuncAttributeMaxDynamicSharedMemorySize, gemm_smem);
        cudaFuncSetAttribute(attn_mma_kernel,
                             cudaFuncAttributeMaxDynamicSharedMemorySize, attn_smem);
        attr_set = 1;
    }

    dim3 tgrid(Pp / 32, Dd / 32);
    dim3 tblk(32, 8);

    // fused activation split (q|k|v)
    split3_kernel<<<3 * 8192, 256>>>(query, key, value,
                                     (__nv_bfloat162*)a3hi, (__nv_bfloat162*)a3lo);
    // weight transpose+split (Wq|Wk|Wv into 3-segment buffer, Wo separate)
    tsplit_kernel<<<tgrid, tblk>>>(Wq, w3hi,               w3lo);
    tsplit_kernel<<<tgrid, tblk>>>(Wk, w3hi + Dd*Pp,       w3lo + Dd*Pp);
    tsplit_kernel<<<tgrid, tblk>>>(Wv, w3hi + 2*Dd*Pp,     w3lo + 2*Dd*Pp);
    tsplit_kernel<<<tgrid, tblk>>>(Wo, wohi,               wolo);

    // fused QKV projection: grid (24, 64)
    dim3 qkvgrid(3 * Pp / 128, Mm / 128);
    gemm_mma_kernel<<<qkvgrid, 256, gemm_smem>>>(
        a3hi, a3lo, w3hi, w3lo, bq, bk, bv,
        nullptr, qkvhi, qkvlo, 1);

    // attention
    const size_t seg = (size_t)Bb * Hh * Ss * KD;
    dim3 agrid(Ss / 128, Bb * Hh);
    attn_mma_kernel<<<agrid, 256, attn_smem>>>(
        qkvhi, qkvlo, qkvhi + seg, qkvlo + seg, qkvhi + 2*seg, qkvlo + 2*seg,
        athi, atlo);

    // output projection: grid (8, 64)
    dim3 ogrid(Pp / 128, Mm / 128);
    gemm_mma_kernel<<<ogrid, 256, gemm_smem>>>(
        athi, atlo, wohi, wolo, bo, bo, bo,
        out, nullptr, nullptr, 0);
}